// round 7
// baseline (speedup 1.0000x reference)
#include <cuda_runtime.h>
#include <math.h>

#define B_   64
#define T_   1024
#define D_   256
#define H_   1024
#define G4   4096   // 4*H
#define NBLK 128
#define NTHR 256

typedef unsigned long long ull;

// fma.rn.f32x2: two independent IEEE fp32 FMAs in one instruction (FFMA2 SASS).
__device__ __forceinline__ void fma2(ull &d, ull a, ull b) {
    asm("fma.rn.f32x2 %0, %1, %2, %3;" : "=l"(d) : "l"(a), "l"(b), "l"(d));
}
__device__ __forceinline__ float f2_lo(ull v) { return __uint_as_float((unsigned)v); }
__device__ __forceinline__ float f2_hi(ull v) { return __uint_as_float((unsigned)(v >> 32)); }

// ---------------- scratch (static device allocations; no cudaMalloc) ----------------
__device__ float g_xg[(size_t)B_ * T_ * G4];     // 1 GiB, reused by both layers
__device__ float g_y0[(size_t)B_ * T_ * H_];     // 256 MB layer-0 outputs
__device__ float g_WT_ih0[(size_t)D_ * G4];      // [K][4H] transposed weights
__device__ float g_WT_hh0[(size_t)H_ * G4];
__device__ float g_WT_ih1[(size_t)H_ * G4];
__device__ float g_WT_hh1[(size_t)H_ * G4];
__device__ float g_hA[B_ * H_];                  // h ping-pong
__device__ float g_hB[B_ * H_];
__device__ float g_c[B_ * H_];                   // final c only
__device__ unsigned g_bar_cnt;                   // grid barrier (monotonic)
__device__ unsigned g_bar_gen;

// ---------------- weight transpose: W[4H, K] -> WT[K, 4H] ----------------
__global__ void transpose_k(const float* __restrict__ W, int K, int which) {
    float* WT = (which == 0) ? g_WT_ih0 :
                (which == 1) ? g_WT_hh0 :
                (which == 2) ? g_WT_ih1 : g_WT_hh1;
    __shared__ float tile[32][33];
    int c0 = blockIdx.x * 32;   // K dim
    int r0 = blockIdx.y * 32;   // 4H dim
    #pragma unroll
    for (int i = 0; i < 32; i += 8)
        tile[threadIdx.y + i][threadIdx.x] =
            W[(size_t)(r0 + threadIdx.y + i) * K + c0 + threadIdx.x];
    __syncthreads();
    #pragma unroll
    for (int i = 0; i < 32; i += 8)
        WT[(size_t)(c0 + threadIdx.y + i) * G4 + r0 + threadIdx.x] =
            tile[threadIdx.x][threadIdx.y + i];
}

// ---------------- xg GEMM: g_xg[M,4096] = X[M,K] @ WT[K,4096] + b1 + b2 ----------------
// BM=128, BN=64, BK=16, 256 threads, 8x4 microtile via FFMA2 (acc2[8][2]).
// A is stored DUPLICATED in SMEM (each value twice) so the splat operand is a
// single 8B load; B columns pair naturally from LDS.128.
// XS: BM=128 rows duplicated = 256 floats/row + 2 pad (even => 8B-aligned LDS.64).
// (R5 bug: XS=134 overflowed into following k-rows and corrupted As2.)
#define XS 258
__global__ void __launch_bounds__(256)
gemm_xg(const float* __restrict__ Xin, int K, int which,
        const float* __restrict__ b1, const float* __restrict__ b2) {
    const float* __restrict__ X  = (which == 1) ? g_y0 : Xin;
    const float* __restrict__ WT = (which == 1) ? g_WT_ih1 : g_WT_ih0;

    __shared__ float As2[2][16 * XS];   // [k][2m] duplicated
    __shared__ float Bs[2][16 * 64];    // [k][n]

    int tid = threadIdx.x;
    size_t m0 = (size_t)blockIdx.y * 128;
    int n0 = blockIdx.x * 64;
    int cx = tid & 15, ry = tid >> 4;
    int c0 = cx * 4, r0 = ry * 8;

    ull acc2[8][2] = {};
    float4 ra[2], rb;

    // prolog: load chunk 0
    #pragma unroll
    for (int p = 0; p < 2; p++) {
        int idx = tid + p * 256;
        int m = idx >> 2, kq = idx & 3;
        ra[p] = *(const float4*)&X[(m0 + m) * K + kq * 4];
    }
    {
        int n4 = tid & 15, k = tid >> 4;
        rb = *(const float4*)&WT[(size_t)k * G4 + n0 + n4 * 4];
    }
    #pragma unroll
    for (int p = 0; p < 2; p++) {
        int idx = tid + p * 256;
        int m = idx >> 2, kq = idx & 3;
        float v[4] = {ra[p].x, ra[p].y, ra[p].z, ra[p].w};
        #pragma unroll
        for (int j = 0; j < 4; j++)
            *(float2*)&As2[0][(kq * 4 + j) * XS + 2 * m] = make_float2(v[j], v[j]);
    }
    {
        int n4 = tid & 15, k = tid >> 4;
        *(float4*)&Bs[0][k * 64 + n4 * 4] = rb;
    }

    int buf = 0;
    for (int kk = 0; kk < K; kk += 16) {
        __syncthreads();
        bool more = (kk + 16) < K;
        if (more) {
            #pragma unroll
            for (int p = 0; p < 2; p++) {
                int idx = tid + p * 256;
                int m = idx >> 2, kq = idx & 3;
                ra[p] = *(const float4*)&X[(m0 + m) * K + kk + 16 + kq * 4];
            }
            int n4 = tid & 15, k = tid >> 4;
            rb = *(const float4*)&WT[(size_t)(kk + 16 + k) * G4 + n0 + n4 * 4];
        }
        #pragma unroll
        for (int k = 0; k < 16; k++) {
            ulonglong2 bp = *(const ulonglong2*)&Bs[buf][k * 64 + c0];
            #pragma unroll
            for (int i = 0; i < 8; i++) {
                ull ap = *(const ull*)&As2[buf][k * XS + 2 * (r0 + i)];
                fma2(acc2[i][0], ap, bp.x);
                fma2(acc2[i][1], ap, bp.y);
            }
        }
        if (more) {
            #pragma unroll
            for (int p = 0; p < 2; p++) {
                int idx = tid + p * 256;
                int m = idx >> 2, kq = idx & 3;
                float v[4] = {ra[p].x, ra[p].y, ra[p].z, ra[p].w};
                #pragma unroll
                for (int j = 0; j < 4; j++)
                    *(float2*)&As2[buf ^ 1][(kq * 4 + j) * XS + 2 * m] = make_float2(v[j], v[j]);
            }
            int n4 = tid & 15, k = tid >> 4;
            *(float4*)&Bs[buf ^ 1][k * 64 + n4 * 4] = rb;
            buf ^= 1;
        }
    }

    float bias[4];
    #pragma unroll
    for (int j = 0; j < 4; j++)
        bias[j] = b1[n0 + c0 + j] + b2[n0 + c0 + j];
    #pragma unroll
    for (int i = 0; i < 8; i++) {
        float4 o;
        o.x = f2_lo(acc2[i][0]) + bias[0];
        o.y = f2_hi(acc2[i][0]) + bias[1];
        o.z = f2_lo(acc2[i][1]) + bias[2];
        o.w = f2_hi(acc2[i][1]) + bias[3];
        *(float4*)&g_xg[(m0 + r0 + i) * G4 + n0 + c0] = o;
    }
}

// ---------------- zero h (read buffer) and barrier state ----------------
__global__ void zero_state() {
    int i = blockIdx.x * blockDim.x + threadIdx.x;
    if (i < B_ * H_) g_hA[i] = 0.f;
    if (i == 0) { g_bar_cnt = 0u; g_bar_gen = 0u; }
}

// ---------------- grid-wide barrier (all 128 blocks resident) ----------------
__device__ __forceinline__ void grid_sync(unsigned target) {
    __threadfence();
    __syncthreads();
    if (threadIdx.x == 0) {
        unsigned arrived = atomicAdd(&g_bar_cnt, 1u) + 1u;
        if ((arrived & (NBLK - 1)) == 0u) {
            atomicExch(&g_bar_gen, arrived >> 7);   // 128 arrivals per generation
        } else {
            while (*(volatile unsigned*)&g_bar_gen < target) __nanosleep(32);
        }
        __threadfence();
    }
    __syncthreads();
}

// ---------------- persistent LSTM recurrence: all 1024 steps in one kernel ----------------
// 128 blocks x 256 threads. Block owns j0..j0+7 (8 h-cols = 32 gate-cols).
// W_hh slice (32 cols x 1024 K = 128KB) cached in SMEM for the whole kernel.
// K split in two halves (512 each) across the two 128-thread groups.
// Inner product via FFMA2: h duplicated in SMEM (pre-splatted), W pairs natural.
extern __shared__ float smem[];
#define AS_STRIDE 138   // 64 batch rows duplicated = 128 floats + pad; even => 8B aligned
// layout: Ws [1024*32] | As2 [2 half][2 buf][32 k][138] | Gs [2 half][32 c][64 b]
#define WS(k, c)           smem[(k) * 32 + (c)]
#define AS2(h, bf, k, b2)  smem[32768 + ((((h) * 2 + (bf)) * 32 + (k)) * AS_STRIDE) + (b2)]
#define GS(h, c, b)        smem[50432 + (((h) * 32 + (c)) * 64) + (b)]
#define SMEM_BYTES         ((32768 + 17664 + 4096) * 4)   // 218112

__global__ void __launch_bounds__(NTHR, 1)
lstm_persist(int layer) {
    const float* __restrict__ WT = layer ? g_WT_hh1 : g_WT_hh0;
    int tid = threadIdx.x;
    int j0 = blockIdx.x * 8;

    // ---- one-time W_hh slice preload: Ws[k][c], c = gate*8 + jj ----
    for (int idx = tid; idx < 32 * H_; idx += NTHR) {
        int c = idx & 31, k = idx >> 5;
        WS(k, c) = WT[(size_t)k * G4 + (c >> 3) * H_ + j0 + (c & 7)];
    }

    int half = tid >> 7;        // K range [half*512, half*512+512)
    int t128 = tid & 127;
    int cx = t128 & 7,  c0 = cx * 4;
    int by = t128 >> 3, b0 = by * 4;
    int kofs = half * 512;

    // cell state in registers: thread owns cells idx = tid + p*256 (p<2)
    float creg[2] = {0.f, 0.f};

    __syncthreads();

    for (int t = 0; t < T_; t++) {
        const float* __restrict__ hsrc = (t & 1) ? g_hB : g_hA;
        float* __restrict__       hdst = (t & 1) ? g_hA : g_hB;

        ull acc2[4][2] = {};
        float ra[16];

        // prolog: chunk 0 of this half's K range
        #pragma unroll
        for (int p = 0; p < 16; p++) {
            int idx = t128 + p * 128;           // 0..2047: b = idx>>5, k = idx&31
            ra[p] = __ldcg(&hsrc[(idx >> 5) * H_ + kofs + (idx & 31)]);
        }
        #pragma unroll
        for (int p = 0; p < 16; p++) {
            int idx = t128 + p * 128;
            *(float2*)&AS2(half, 0, idx & 31, 2 * (idx >> 5)) = make_float2(ra[p], ra[p]);
        }

        int buf = 0;
        for (int kc = 0; kc < 512; kc += 32) {
            __syncthreads();
            bool more = (kc + 32) < 512;
            if (more) {
                #pragma unroll
                for (int p = 0; p < 16; p++) {
                    int idx = t128 + p * 128;
                    ra[p] = __ldcg(&hsrc[(idx >> 5) * H_ + kofs + kc + 32 + (idx & 31)]);
                }
            }
            #pragma unroll
            for (int k = 0; k < 32; k++) {
                ulonglong2 wp = *(const ulonglong2*)&WS(kofs + kc + k, c0);
                #pragma unroll
                for (int bi = 0; bi < 4; bi++) {
                    ull ap = *(const ull*)&AS2(half, buf, k, 2 * (b0 + bi));
                    fma2(acc2[bi][0], ap, wp.x);
                    fma2(acc2[bi][1], ap, wp.y);
                }
            }
            if (more) {
                #pragma unroll
                for (int p = 0; p < 16; p++) {
                    int idx = t128 + p * 128;
                    *(float2*)&AS2(half, buf ^ 1, idx & 31, 2 * (idx >> 5)) =
                        make_float2(ra[p], ra[p]);
                }
                buf ^= 1;
            }
        }

        // ---- exchange partial gates through SMEM (per-half, summed at read) ----
        #pragma unroll
        for (int bi = 0; bi < 4; bi++) {
            GS(half, c0 + 0, b0 + bi) = f2_lo(acc2[bi][0]);
            GS(half, c0 + 1, b0 + bi) = f2_hi(acc2[bi][0]);
            GS(half, c0 + 2, b0 + bi) = f2_lo(acc2[bi][1]);
            GS(half, c0 + 3, b0 + bi) = f2_hi(acc2[bi][1]);
        }
        __syncthreads();

        // ---- pointwise gates: 512 cells, 2 per thread (stable ownership => c in regs) ----
        #pragma unroll
        for (int p = 0; p < 2; p++) {
            int idx = tid + p * 256;            // 0..511
            int jj = idx & 7, b = idx >> 3;
            int j = j0 + jj;
            size_t xb = ((size_t)b * T_ + t) * G4 + j;
            float gi = GS(0, 0 * 8 + jj, b) + GS(1, 0 * 8 + jj, b) + g_xg[xb];
            float gf = GS(0, 1 * 8 + jj, b) + GS(1, 1 * 8 + jj, b) + g_xg[xb + H_];
            float gg = GS(0, 2 * 8 + jj, b) + GS(1, 2 * 8 + jj, b) + g_xg[xb + 2 * H_];
            float go = GS(0, 3 * 8 + jj, b) + GS(1, 3 * 8 + jj, b) + g_xg[xb + 3 * H_];
            float iv = 1.f / (1.f + __expf(-gi));
            float fv = 1.f / (1.f + __expf(-gf));
            float gv = tanhf(gg);
            float ov = 1.f / (1.f + __expf(-go));
            float cn = fv * creg[p] + iv * gv;
            creg[p] = cn;
            float hn = ov * tanhf(cn);
            int hc = b * H_ + j;
            hdst[hc] = hn;
            if (layer == 0)
                g_y0[((size_t)b * T_ + t) * H_ + j] = hn;
            if (t == T_ - 1)
                g_c[hc] = cn;
        }

        if (t + 1 < T_)
            grid_sync((unsigned)(t + 1));
    }
}

// ---------------- write final h, c for one layer into d_out ----------------
// out layout: h[2][B][H] then c[2][B][H]. Final h is in g_hA (T=1024 even).
__global__ void copy_out(float* __restrict__ out, int layer) {
    int i = blockIdx.x * blockDim.x + threadIdx.x;
    if (i < B_ * H_) {
        out[(size_t)layer * B_ * H_ + i]       = g_hA[i];
        out[(size_t)(2 + layer) * B_ * H_ + i] = g_c[i];
    }
}

// ---------------- host ----------------
extern "C" void kernel_launch(void* const* d_in, const int* in_sizes, int n_in,
                              void* d_out, int out_size) {
    const float* x     = (const float*)d_in[0];
    const float* W_ih0 = (const float*)d_in[1];
    const float* W_hh0 = (const float*)d_in[2];
    const float* b_ih0 = (const float*)d_in[3];
    const float* b_hh0 = (const float*)d_in[4];
    const float* W_ih1 = (const float*)d_in[5];
    const float* W_hh1 = (const float*)d_in[6];
    const float* b_ih1 = (const float*)d_in[7];
    const float* b_hh1 = (const float*)d_in[8];
    float* out = (float*)d_out;

    cudaFuncSetAttribute(lstm_persist,
                         cudaFuncAttributeMaxDynamicSharedMemorySize, SMEM_BYTES);

    dim3 tb(32, 8);
    transpose_k<<<dim3(D_ / 32, G4 / 32), tb>>>(W_ih0, D_, 0);
    transpose_k<<<dim3(H_ / 32, G4 / 32), tb>>>(W_hh0, H_, 1);
    transpose_k<<<dim3(H_ / 32, G4 / 32), tb>>>(W_ih1, H_, 2);
    transpose_k<<<dim3(H_ / 32, G4 / 32), tb>>>(W_hh1, H_, 3);

    // ---- layer 0 ----
    gemm_xg<<<dim3(G4 / 64, (B_ * T_) / 128), 256>>>(x, D_, 0, b_ih0, b_hh0);
    zero_state<<<256, 256>>>();
    lstm_persist<<<NBLK, NTHR, SMEM_BYTES>>>(0);
    copy_out<<<256, 256>>>(out, 0);

    // ---- layer 1 ----
    gemm_xg<<<dim3(G4 / 64, (B_ * T_) / 128), 256>>>(nullptr, H_, 1, b_ih1, b_hh1);
    zero_state<<<256, 256>>>();
    lstm_persist<<<NBLK, NTHR, SMEM_BYTES>>>(1);
    copy_out<<<256, 256>>>(out, 1);
}

// round 11
// speedup vs baseline: 1.2596x; 1.2596x over previous
#include <cuda_runtime.h>
#include <cuda_bf16.h>
#include <math.h>

#define B_   64
#define T_   1024
#define D_   256
#define H_   1024
#define G4   4096   // 4*H
#define NBLK 128
#define NTHR 256

typedef unsigned long long ull;

// ---------------- scratch (static device allocations; no cudaMalloc) ----------------
__device__ float g_xg[(size_t)B_ * T_ * G4];     // 1 GiB, reused by both layers
__device__ float g_y0[(size_t)B_ * T_ * H_];     // 256 MB layer-0 outputs
__device__ float g_WT_hh0[(size_t)H_ * G4];      // [K][4H] transposed hh weights
__device__ float g_WT_hh1[(size_t)H_ * G4];
__device__ __nv_bfloat16 g_xhi[(size_t)B_ * T_ * H_];   // split activations (max K=1024)
__device__ __nv_bfloat16 g_xlo[(size_t)B_ * T_ * H_];
__device__ __nv_bfloat16 g_whi[(size_t)G4 * H_];        // split ih weights (reused per layer)
__device__ __nv_bfloat16 g_wlo[(size_t)G4 * H_];
__device__ float g_hA[B_ * H_];                  // h ping-pong
__device__ float g_hB[B_ * H_];
__device__ float g_c[B_ * H_];                   // final c only
__device__ unsigned g_bar_cnt;                   // grid barrier (monotonic)
__device__ unsigned g_bar_gen;

// ---------------- base-ISA tensor helpers (sm_80+: compile on plain sm_103) --------
__device__ __forceinline__ unsigned smem_u32(const void* p) {
    unsigned a;
    asm("{ .reg .u64 t; cvta.to.shared.u64 t, %1; cvt.u32.u64 %0, t; }" : "=r"(a) : "l"(p));
    return a;
}
__device__ __forceinline__ void cpasync16(unsigned dst, const void* src) {
    asm volatile("cp.async.cg.shared.global [%0], [%1], 16;" :: "r"(dst), "l"(src) : "memory");
}
#define CP_COMMIT() asm volatile("cp.async.commit_group;" ::: "memory")
#define CP_WAIT1()  asm volatile("cp.async.wait_group 1;" ::: "memory")
#define CP_WAIT0()  asm volatile("cp.async.wait_group 0;" ::: "memory")

__device__ __forceinline__ void ldsm4(unsigned* r, unsigned addr) {
    asm volatile("ldmatrix.sync.aligned.m8n8.x4.shared.b16 {%0,%1,%2,%3}, [%4];"
                 : "=r"(r[0]), "=r"(r[1]), "=r"(r[2]), "=r"(r[3]) : "r"(addr));
}
__device__ __forceinline__ void mma16816(float* c, const unsigned* a, unsigned b0, unsigned b1) {
    asm volatile(
        "mma.sync.aligned.m16n8k16.row.col.f32.bf16.bf16.f32 "
        "{%0,%1,%2,%3}, {%4,%5,%6,%7}, {%8,%9}, {%0,%1,%2,%3};"
        : "+f"(c[0]), "+f"(c[1]), "+f"(c[2]), "+f"(c[3])
        : "r"(a[0]), "r"(a[1]), "r"(a[2]), "r"(a[3]), "r"(b0), "r"(b1));
}

// ---------------- split fp32 -> bf16 hi + bf16 lo ----------------
// use_y0: select g_y0 INSIDE the kernel (device-global addresses must never be
// taken in host code — host shadow symbol reads silently via ATS on GB300).
__global__ void split_x(const float* __restrict__ src_ext, int use_y0, size_t n) {
    const float* __restrict__ src = use_y0 ? g_y0 : src_ext;
    size_t i = (size_t)blockIdx.x * blockDim.x + threadIdx.x;
    size_t stride = (size_t)gridDim.x * blockDim.x;
    for (; i < n; i += stride) {
        float x = src[i];
        __nv_bfloat16 h = __float2bfloat16(x);
        g_xhi[i] = h;
        g_xlo[i] = __float2bfloat16(x - __bfloat162float(h));
    }
}
__global__ void split_w(const float* __restrict__ src, size_t n) {
    size_t i = (size_t)blockIdx.x * blockDim.x + threadIdx.x;
    size_t stride = (size_t)gridDim.x * blockDim.x;
    for (; i < n; i += stride) {
        float x = src[i];
        __nv_bfloat16 h = __float2bfloat16(x);
        g_whi[i] = h;
        g_wlo[i] = __float2bfloat16(x - __bfloat162float(h));
    }
}

// ---------------- weight transpose (hh only): W[4H, K] -> WT[K, 4H] ----------------
__global__ void transpose_k(const float* __restrict__ W, int K, int which) {
    float* WT = (which == 0) ? g_WT_hh0 : g_WT_hh1;
    __shared__ float tile[32][33];
    int c0 = blockIdx.x * 32;   // K dim
    int r0 = blockIdx.y * 32;   // 4H dim
    #pragma unroll
    for (int i = 0; i < 32; i += 8)
        tile[threadIdx.y + i][threadIdx.x] =
            W[(size_t)(r0 + threadIdx.y + i) * K + c0 + threadIdx.x];
    __syncthreads();
    #pragma unroll
    for (int i = 0; i < 32; i += 8)
        WT[(size_t)(c0 + threadIdx.y + i) * G4 + r0 + threadIdx.x] =
            tile[threadIdx.x][threadIdx.y + i];
}

// ---------------- xg GEMM via mma.sync bf16x3: g_xg[M,4096] = X@W^T + b1 + b2 ------
// BM=128, BN=128, BK=32; 8 warps (2 M x 4 N), warp tile 64x32.
// smem tiles: [row][80B stride] K-major, conflict-free LDSM; cp.async double-buffered.
// Terms: Xhi*Whi + Xlo*Whi + Xhi*Wlo, fp32 accumulators.
#define TILE_B  10240                 // 128 rows * 80 B
#define STAGE_B (4 * TILE_B)          // Ahi, Alo, Bhi, Blo
#define GXM_SMEM (512 + 2 * STAGE_B)  // bias + 2 stages = 82432
__global__ void __launch_bounds__(256, 1)
gemm_xg_mma(int K, const float* __restrict__ b1, const float* __restrict__ b2) {
    extern __shared__ char smx[];
    unsigned sb = smem_u32(smx);
    int tid = threadIdx.x, lane = tid & 31, wid = tid >> 5;
    int warp_m = wid >> 2, warp_n = wid & 3;
    size_t m0 = (size_t)blockIdx.y * 128;
    int n0 = blockIdx.x * 128;
    float* biass = (float*)smx;
    for (int i = tid; i < 128; i += 256)
        biass[i] = b1[n0 + i] + b2[n0 + i];

    int g = lane >> 3, lr = lane & 7;
    // A: groups (m0-7@k0),(m8-15@k0),(m0-7@k8),(m8-15@k8)
    unsigned a_off = (unsigned)((warp_m * 64 + (g & 1) * 8 + lr) * 80 + (g >> 1) * 16);
    // B: groups (n0-7@k0),(n0-7@k8),(n8-15@k0),(n8-15@k8)
    unsigned b_off = (unsigned)((warp_n * 32 + (g >> 1) * 8 + lr) * 80 + (g & 1) * 16);

    float acc[4][4][4] = {};

    int nch = K >> 5;
    // ---- stage loader: 4 arrays x 512 x 16B via cp.async ----
    #define LOAD_CHUNK(s, kk) do {                                              \
        unsigned base_ = sb + 512 + (s) * STAGE_B;                              \
        _Pragma("unroll")                                                       \
        for (int p = 0; p < 8; p++) {                                           \
            int u = tid + p * 256;                                              \
            int arr = u >> 9, v = u & 511, r = v >> 2, q = v & 3;               \
            unsigned dst = base_ + arr * TILE_B + r * 80 + q * 16;              \
            const __nv_bfloat16* src;                                           \
            if      (arr == 0) src = &g_xhi[(m0 + r) * (size_t)K + (kk) + q * 8]; \
            else if (arr == 1) src = &g_xlo[(m0 + r) * (size_t)K + (kk) + q * 8]; \
            else if (arr == 2) src = &g_whi[(size_t)(n0 + r) * K + (kk) + q * 8]; \
            else               src = &g_wlo[(size_t)(n0 + r) * K + (kk) + q * 8]; \
            cpasync16(dst, src);                                                \
        }                                                                       \
    } while (0)

    LOAD_CHUNK(0, 0);
    CP_COMMIT();

    for (int ch = 0; ch < nch; ch++) {
        if (ch + 1 < nch) {
            LOAD_CHUNK((ch + 1) & 1, (ch + 1) << 5);
            CP_COMMIT();
            CP_WAIT1();
        } else {
            CP_WAIT0();
        }
        __syncthreads();
        unsigned st = sb + 512 + (ch & 1) * STAGE_B;
        #pragma unroll
        for (int ks = 0; ks < 2; ks++) {
            unsigned ahi[4][4], alo[4][4], bhi[2][4], blo[2][4];
            #pragma unroll
            for (int mi = 0; mi < 4; mi++) {
                ldsm4(ahi[mi], st + 0 * TILE_B + a_off + mi * 1280 + ks * 32);
                ldsm4(alo[mi], st + 1 * TILE_B + a_off + mi * 1280 + ks * 32);
            }
            #pragma unroll
            for (int nj = 0; nj < 2; nj++) {
                ldsm4(bhi[nj], st + 2 * TILE_B + b_off + nj * 1280 + ks * 32);
                ldsm4(blo[nj], st + 3 * TILE_B + b_off + nj * 1280 + ks * 32);
            }
            #pragma unroll
            for (int mi = 0; mi < 4; mi++)
                #pragma unroll
                for (int ni = 0; ni < 4; ni++) {
                    unsigned* bh = &bhi[ni >> 1][2 * (ni & 1)];
                    unsigned* bl = &blo[ni >> 1][2 * (ni & 1)];
                    mma16816(acc[mi][ni], ahi[mi], bh[0], bh[1]);
                    mma16816(acc[mi][ni], alo[mi], bh[0], bh[1]);
                    mma16816(acc[mi][ni], ahi[mi], bl[0], bl[1]);
                }
        }
        __syncthreads();
    }
    #undef LOAD_CHUNK

    // ---- epilogue: c frag (m=l/4, n=2*(l%4)), rows +8 in c2,c3 ----
    int qm = lane >> 2, qn = 2 * (lane & 3);
    #pragma unroll
    for (int mi = 0; mi < 4; mi++)
        #pragma unroll
        for (int ni = 0; ni < 4; ni++) {
            int nl = warp_n * 32 + ni * 8 + qn;
            size_t m = m0 + warp_m * 64 + mi * 16 + qm;
            float2 v0 = make_float2(acc[mi][ni][0] + biass[nl],
                                    acc[mi][ni][1] + biass[nl + 1]);
            float2 v1 = make_float2(acc[mi][ni][2] + biass[nl],
                                    acc[mi][ni][3] + biass[nl + 1]);
            *(float2*)&g_xg[m * G4 + n0 + nl] = v0;
            *(float2*)&g_xg[(m + 8) * G4 + n0 + nl] = v1;
        }
}

// ---------------- zero h (read buffer) and barrier state ----------------
__global__ void zero_state() {
    int i = blockIdx.x * blockDim.x + threadIdx.x;
    if (i < B_ * H_) g_hA[i] = 0.f;
    if (i == 0) { g_bar_cnt = 0u; g_bar_gen = 0u; }
}

// ---------------- grid-wide barrier (all 128 blocks resident) ----------------
__device__ __forceinline__ void grid_sync(unsigned target) {
    __threadfence();
    __syncthreads();
    if (threadIdx.x == 0) {
        unsigned arrived = atomicAdd(&g_bar_cnt, 1u) + 1u;
        if ((arrived & (NBLK - 1)) == 0u) {
            atomicExch(&g_bar_gen, arrived >> 7);   // 128 arrivals per generation
        } else {
            while (*(volatile unsigned*)&g_bar_gen < target) __nanosleep(64);
        }
        __threadfence();
    }
    __syncthreads();
}

// ---------------- persistent LSTM recurrence (R4 known-good scalar version) ----------------
extern __shared__ float smem[];
#define WS(k, c)          smem[(k) * 32 + (c)]
#define AS(h, bf, k, b)   smem[32768 + ((((h) * 2 + (bf)) * 32 + (k)) * 68) + (b)]
#define GS(h, c, b)       smem[41472 + (((h) * 32 + (c)) * 64) + (b)]
#define SMEM_BYTES        ((32768 + 8704 + 4096) * 4)   // 182272

__global__ void __launch_bounds__(NTHR, 1)
lstm_persist(int layer) {
    const float* __restrict__ WT = layer ? g_WT_hh1 : g_WT_hh0;
    int tid = threadIdx.x;
    int j0 = blockIdx.x * 8;

    for (int idx = tid; idx < 32 * H_; idx += NTHR) {
        int c = idx & 31, k = idx >> 5;
        WS(k, c) = WT[(size_t)k * G4 + (c >> 3) * H_ + j0 + (c & 7)];
    }

    int half = tid >> 7;
    int t128 = tid & 127;
    int cx = t128 & 7,  c0 = cx * 4;
    int by = t128 >> 3, b0 = by * 4;
    int kofs = half * 512;

    float creg[2] = {0.f, 0.f};

    __syncthreads();

    for (int t = 0; t < T_; t++) {
        const float* __restrict__ hsrc = (t & 1) ? g_hB : g_hA;
        float* __restrict__       hdst = (t & 1) ? g_hA : g_hB;

        float acc[4][4] = {};
        float ra[16];

        #pragma unroll
        for (int p = 0; p < 16; p++) {
            int idx = t128 + p * 128;
            ra[p] = __ldcg(&hsrc[(idx >> 5) * H_ + kofs + (idx & 31)]);
        }
        #pragma unroll
        for (int p = 0; p < 16; p++) {
            int idx = t128 + p * 128;
            AS(half, 0, idx & 31, idx >> 5) = ra[p];
        }

        int buf = 0;
        for (int kc = 0; kc < 512; kc += 32) {
            __syncthreads();
            bool more = (kc + 32) < 512;
            if (more) {
                #pragma unroll
                for (int p = 0; p < 16; p++) {
                    int idx = t128 + p * 128;
                    ra[p] = __ldcg(&hsrc[(idx >> 5) * H_ + kofs + kc + 32 + (idx & 31)]);
                }
            }
            #pragma unroll
            for (int k = 0; k < 32; k++) {
                float4 wv = *(const float4*)&WS(kofs + kc + k, c0);
                float4 av = *(const float4*)&AS(half, buf, k, b0);
                float am[4] = {av.x, av.y, av.z, av.w};
                float wn[4] = {wv.x, wv.y, wv.z, wv.w};
                #pragma unroll
                for (int bi = 0; bi < 4; bi++)
                    #pragma unroll
                    for (int ci = 0; ci < 4; ci++)
                        acc[bi][ci] += am[bi] * wn[ci];
            }
            if (more) {
                #pragma unroll
                for (int p = 0; p < 16; p++) {
                    int idx = t128 + p * 128;
                    AS(half, buf ^ 1, idx & 31, idx >> 5) = ra[p];
                }
                buf ^= 1;
            }
        }

        #pragma unroll
        for (int ci = 0; ci < 4; ci++)
            #pragma unroll
            for (int bi = 0; bi < 4; bi++)
                GS(half, c0 + ci, b0 + bi) = acc[bi][ci];
        __syncthreads();

        #pragma unroll
        for (int p = 0; p < 2; p++) {
            int idx = tid + p * 256;
            int jj = idx & 7, b = idx >> 3;
            int j = j0 + jj;
            size_t xb = ((size_t)b * T_ + t) * G4 + j;
            float gi = GS(0, 0 * 8 + jj, b) + GS(1, 0 * 8 + jj, b) + g_xg[xb];
            float gf = GS(0, 1 * 8 + jj, b) + GS(1, 1 * 8 + jj, b) + g_xg[xb + H_];
            float gg = GS(0, 2 * 8 + jj, b) + GS(1, 2 * 8 + jj, b) + g_xg[xb + 2 * H_];
            float go = GS(0, 3 * 8 + jj, b) + GS(1, 3 * 8 + jj, b) + g_xg[xb + 3 * H_];
            float iv = 1.f / (1.f + __expf(-gi));
            float fv = 1.f / (1.f + __expf(-gf));
            float gv = tanhf(gg);
            float ov = 1.f / (1.f + __expf(-go));
            float cn = fv * creg[p] + iv * gv;
            creg[p] = cn;
            float hn = ov * tanhf(cn);
            int hc = b * H_ + j;
            hdst[hc] = hn;
            if (layer == 0)
                g_y0[((size_t)b * T_ + t) * H_ + j] = hn;
            if (t == T_ - 1)
                g_c[hc] = cn;
        }

        if (t + 1 < T_)
            grid_sync((unsigned)(t + 1));
    }
}

// ---------------- write final h, c for one layer into d_out ----------------
__global__ void copy_out(float* __restrict__ out, int layer) {
    int i = blockIdx.x * blockDim.x + threadIdx.x;
    if (i < B_ * H_) {
        out[(size_t)layer * B_ * H_ + i]       = g_hA[i];
        out[(size_t)(2 + layer) * B_ * H_ + i] = g_c[i];
    }
}

// ---------------- host ----------------
extern "C" void kernel_launch(void* const* d_in, const int* in_sizes, int n_in,
                              void* d_out, int out_size) {
    const float* x     = (const float*)d_in[0];
    const float* W_ih0 = (const float*)d_in[1];
    const float* W_hh0 = (const float*)d_in[2];
    const float* b_ih0 = (const float*)d_in[3];
    const float* b_hh0 = (const float*)d_in[4];
    const float* W_ih1 = (const float*)d_in[5];
    const float* W_hh1 = (const float*)d_in[6];
    const float* b_ih1 = (const float*)d_in[7];
    const float* b_hh1 = (const float*)d_in[8];
    float* out = (float*)d_out;

    cudaFuncSetAttribute(lstm_persist,
                         cudaFuncAttributeMaxDynamicSharedMemorySize, SMEM_BYTES);
    cudaFuncSetAttribute(gemm_xg_mma,
                         cudaFuncAttributeMaxDynamicSharedMemorySize, GXM_SMEM);

    dim3 tb(32, 8);
    transpose_k<<<dim3(H_ / 32, G4 / 32), tb>>>(W_hh0, H_, 0);
    transpose_k<<<dim3(H_ / 32, G4 / 32), tb>>>(W_hh1, H_, 1);

    // ---- layer 0 ----
    split_x<<<4096, 256>>>(x, 0, (size_t)B_ * T_ * D_);
    split_w<<<1024, 256>>>(W_ih0, (size_t)G4 * D_);
    gemm_xg_mma<<<dim3(G4 / 128, (B_ * T_) / 128), 256, GXM_SMEM>>>(D_, b_ih0, b_hh0);
    zero_state<<<256, 256>>>();
    lstm_persist<<<NBLK, NTHR, SMEM_BYTES>>>(0);
    copy_out<<<256, 256>>>(out, 0);

    // ---- layer 1 ----
    split_x<<<4096, 256>>>(nullptr, 1, (size_t)B_ * T_ * H_);
    split_w<<<4096, 256>>>(W_ih1, (size_t)G4 * H_);
    gemm_xg_mma<<<dim3(G4 / 128, (B_ * T_) / 128), 256, GXM_SMEM>>>(H_, b_ih1, b_hh1);
    zero_state<<<256, 256>>>();
    lstm_persist<<<NBLK, NTHR, SMEM_BYTES>>>(1);
    copy_out<<<256, 256>>>(out, 1);
}

// round 12
// speedup vs baseline: 2.4118x; 1.9148x over previous
#include <cuda_runtime.h>
#include <cuda_bf16.h>
#include <math.h>

#define B_   64
#define T_   1024
#define D_   256
#define H_   1024
#define G4   4096   // 4*H
#define NBLK 128
#define NTHR 256

typedef unsigned long long ull;

// ---------------- scratch (static device allocations; no cudaMalloc) ----------------
__device__ float g_xg[(size_t)B_ * T_ * G4];     // 1 GiB, reused by both layers
__device__ float g_y0[(size_t)B_ * T_ * H_];     // 256 MB layer-0 outputs
__device__ __nv_bfloat16 g_xhi[(size_t)B_ * T_ * H_];   // split activations (max K=1024)
__device__ __nv_bfloat16 g_xlo[(size_t)B_ * T_ * H_];
__device__ __nv_bfloat16 g_whi[(size_t)G4 * H_];        // split ih weights (reused per layer)
__device__ __nv_bfloat16 g_wlo[(size_t)G4 * H_];
__device__ __nv_bfloat16 g_hsp[2][2][B_ * H_];   // h bf16 split ping-pong [parity][hi/lo]
__device__ float g_hfin[B_ * H_];                // final h (t = T-1)
__device__ float g_c[B_ * H_];                   // final c
__device__ unsigned g_bar_cnt;                   // grid barrier (monotonic)
__device__ unsigned g_bar_gen;

// ---------------- base-ISA tensor helpers (sm_80+: compile on plain sm_103) --------
__device__ __forceinline__ unsigned smem_u32(const void* p) {
    unsigned a;
    asm("{ .reg .u64 t; cvta.to.shared.u64 t, %1; cvt.u32.u64 %0, t; }" : "=r"(a) : "l"(p));
    return a;
}
__device__ __forceinline__ void cpasync16(unsigned dst, const void* src) {
    asm volatile("cp.async.cg.shared.global [%0], [%1], 16;" :: "r"(dst), "l"(src) : "memory");
}
#define CP_COMMIT() asm volatile("cp.async.commit_group;" ::: "memory")
#define CP_WAIT1()  asm volatile("cp.async.wait_group 1;" ::: "memory")
#define CP_WAIT0()  asm volatile("cp.async.wait_group 0;" ::: "memory")

__device__ __forceinline__ void ldsm4(unsigned* r, unsigned addr) {
    asm volatile("ldmatrix.sync.aligned.m8n8.x4.shared.b16 {%0,%1,%2,%3}, [%4];"
                 : "=r"(r[0]), "=r"(r[1]), "=r"(r[2]), "=r"(r[3]) : "r"(addr));
}
__device__ __forceinline__ void mma16816(float* c, const unsigned* a, unsigned b0, unsigned b1) {
    asm volatile(
        "mma.sync.aligned.m16n8k16.row.col.f32.bf16.bf16.f32 "
        "{%0,%1,%2,%3}, {%4,%5,%6,%7}, {%8,%9}, {%0,%1,%2,%3};"
        : "+f"(c[0]), "+f"(c[1]), "+f"(c[2]), "+f"(c[3])
        : "r"(a[0]), "r"(a[1]), "r"(a[2]), "r"(a[3]), "r"(b0), "r"(b1));
}

// ---------------- split fp32 -> bf16 hi + bf16 lo ----------------
__global__ void split_x(const float* __restrict__ src_ext, int use_y0, size_t n) {
    const float* __restrict__ src = use_y0 ? g_y0 : src_ext;
    size_t i = (size_t)blockIdx.x * blockDim.x + threadIdx.x;
    size_t stride = (size_t)gridDim.x * blockDim.x;
    for (; i < n; i += stride) {
        float x = src[i];
        __nv_bfloat16 h = __float2bfloat16(x);
        g_xhi[i] = h;
        g_xlo[i] = __float2bfloat16(x - __bfloat162float(h));
    }
}
__global__ void split_w(const float* __restrict__ src, size_t n) {
    size_t i = (size_t)blockIdx.x * blockDim.x + threadIdx.x;
    size_t stride = (size_t)gridDim.x * blockDim.x;
    for (; i < n; i += stride) {
        float x = src[i];
        __nv_bfloat16 h = __float2bfloat16(x);
        g_whi[i] = h;
        g_wlo[i] = __float2bfloat16(x - __bfloat162float(h));
    }
}

// ---------------- xg GEMM via mma.sync bf16x3 (R11, validated) ----------------------
#define TILE_B  10240
#define STAGE_B (4 * TILE_B)
#define GXM_SMEM (512 + 2 * STAGE_B)
__global__ void __launch_bounds__(256, 1)
gemm_xg_mma(int K, const float* __restrict__ b1, const float* __restrict__ b2) {
    extern __shared__ char smx[];
    unsigned sb = smem_u32(smx);
    int tid = threadIdx.x, lane = tid & 31, wid = tid >> 5;
    int warp_m = wid >> 2, warp_n = wid & 3;
    size_t m0 = (size_t)blockIdx.y * 128;
    int n0 = blockIdx.x * 128;
    float* biass = (float*)smx;
    for (int i = tid; i < 128; i += 256)
        biass[i] = b1[n0 + i] + b2[n0 + i];

    int g = lane >> 3, lr = lane & 7;
    unsigned a_off = (unsigned)((warp_m * 64 + (g & 1) * 8 + lr) * 80 + (g >> 1) * 16);
    unsigned b_off = (unsigned)((warp_n * 32 + (g >> 1) * 8 + lr) * 80 + (g & 1) * 16);

    float acc[4][4][4] = {};
    int nch = K >> 5;
    #define LOAD_CHUNK(s, kk) do {                                              \
        unsigned base_ = sb + 512 + (s) * STAGE_B;                              \
        _Pragma("unroll")                                                       \
        for (int p = 0; p < 8; p++) {                                           \
            int u = tid + p * 256;                                              \
            int arr = u >> 9, v = u & 511, r = v >> 2, q = v & 3;               \
            unsigned dst = base_ + arr * TILE_B + r * 80 + q * 16;              \
            const __nv_bfloat16* src;                                           \
            if      (arr == 0) src = &g_xhi[(m0 + r) * (size_t)K + (kk) + q * 8]; \
            else if (arr == 1) src = &g_xlo[(m0 + r) * (size_t)K + (kk) + q * 8]; \
            else if (arr == 2) src = &g_whi[(size_t)(n0 + r) * K + (kk) + q * 8]; \
            else               src = &g_wlo[(size_t)(n0 + r) * K + (kk) + q * 8]; \
            cpasync16(dst, src);                                                \
        }                                                                       \
    } while (0)

    LOAD_CHUNK(0, 0);
    CP_COMMIT();

    for (int ch = 0; ch < nch; ch++) {
        if (ch + 1 < nch) {
            LOAD_CHUNK((ch + 1) & 1, (ch + 1) << 5);
            CP_COMMIT();
            CP_WAIT1();
        } else {
            CP_WAIT0();
        }
        __syncthreads();
        unsigned st = sb + 512 + (ch & 1) * STAGE_B;
        #pragma unroll
        for (int ks = 0; ks < 2; ks++) {
            unsigned ahi[4][4], alo[4][4], bhi[2][4], blo[2][4];
            #pragma unroll
            for (int mi = 0; mi < 4; mi++) {
                ldsm4(ahi[mi], st + 0 * TILE_B + a_off + mi * 1280 + ks * 32);
                ldsm4(alo[mi], st + 1 * TILE_B + a_off + mi * 1280 + ks * 32);
            }
            #pragma unroll
            for (int nj = 0; nj < 2; nj++) {
                ldsm4(bhi[nj], st + 2 * TILE_B + b_off + nj * 1280 + ks * 32);
                ldsm4(blo[nj], st + 3 * TILE_B + b_off + nj * 1280 + ks * 32);
            }
            #pragma unroll
            for (int mi = 0; mi < 4; mi++)
                #pragma unroll
                for (int ni = 0; ni < 4; ni++) {
                    unsigned* bh = &bhi[ni >> 1][2 * (ni & 1)];
                    unsigned* bl = &blo[ni >> 1][2 * (ni & 1)];
                    mma16816(acc[mi][ni], ahi[mi], bh[0], bh[1]);
                    mma16816(acc[mi][ni], alo[mi], bh[0], bh[1]);
                    mma16816(acc[mi][ni], ahi[mi], bl[0], bl[1]);
                }
        }
        __syncthreads();
    }
    #undef LOAD_CHUNK

    int qm = lane >> 2, qn = 2 * (lane & 3);
    #pragma unroll
    for (int mi = 0; mi < 4; mi++)
        #pragma unroll
        for (int ni = 0; ni < 4; ni++) {
            int nl = warp_n * 32 + ni * 8 + qn;
            size_t m = m0 + warp_m * 64 + mi * 16 + qm;
            float2 v0 = make_float2(acc[mi][ni][0] + biass[nl],
                                    acc[mi][ni][1] + biass[nl + 1]);
            float2 v1 = make_float2(acc[mi][ni][2] + biass[nl],
                                    acc[mi][ni][3] + biass[nl + 1]);
            *(float2*)&g_xg[m * G4 + n0 + nl] = v0;
            *(float2*)&g_xg[(m + 8) * G4 + n0 + nl] = v1;
        }
}

// ---------------- zero h-split read buffer (parity 0) and barrier state ----------------
__global__ void zero_state() {
    int i = blockIdx.x * blockDim.x + threadIdx.x;
    if (i < B_ * H_) {
        g_hsp[0][0][i] = __float2bfloat16(0.f);
        g_hsp[0][1][i] = __float2bfloat16(0.f);
    }
    if (i == 0) { g_bar_cnt = 0u; g_bar_gen = 0u; }
}

// ---------------- grid-wide barrier (all 128 blocks resident) ----------------
__device__ __forceinline__ void grid_sync(unsigned target) {
    __threadfence();
    __syncthreads();
    if (threadIdx.x == 0) {
        unsigned arrived = atomicAdd(&g_bar_cnt, 1u) + 1u;
        if ((arrived & (NBLK - 1)) == 0u) {
            atomicExch(&g_bar_gen, arrived >> 7);
        } else {
            while (*(volatile unsigned*)&g_bar_gen < target) __nanosleep(64);
        }
        __threadfence();
    }
    __syncthreads();
}

// ---------------- persistent LSTM recurrence, tensorized (mma.sync bf16x3) ------------
// 128 blocks x 256 threads (8 warps = 4m x 2n, warp tile m16 x n16).
// Block owns 8 h-cols = 32 gate cols. W_hh slice bf16 hi/lo resident in SMEM
// (split from fp32 at preload; W_hh[4H][K] is already [n][k] K-major).
// A = h bf16 hi/lo, global ping-pong, streamed per step in 8 K-chunks of 128.
// D = Ahi*Bhi + Alo*Bhi + Ahi*Blo, fp32 accum.
#define WROW   2064                 // 1024*2 + 16 pad (conflict-free LDSM)
#define SMW_HI 0
#define SMW_LO 66048                // 32*2064
#define AROW   272                  // 128*2 + 16 pad
#define ATILE  17408                // 64*272
#define SMA    132096               // 2*32*2064
#define SMG    201728               // SMA + 2 buf * 2 arr * ATILE
#define LP_SMEM 210048              // SMG + 32*65*4
#define GSX(c, b) (*(float*)(sm + SMG + (((c) * 65 + (b)) << 2)))

__global__ void __launch_bounds__(NTHR, 1)
lstm_persist(const float* __restrict__ Whh, int layer) {
    extern __shared__ char sm[];
    unsigned sb = smem_u32(sm);
    int tid = threadIdx.x, lane = tid & 31, wid = tid >> 5;
    int warp_m = wid & 3, warp_n = wid >> 2;
    int j0 = blockIdx.x * 8;

    // ---- one-time W_hh slice preload + fp32->bf16 hi/lo split ----
    for (int idx = tid; idx < 32 * H_; idx += NTHR) {
        int c = idx >> 10, k = idx & 1023;
        float w = Whh[(size_t)((c >> 3) * H_ + j0 + (c & 7)) * H_ + k];
        __nv_bfloat16 hi = __float2bfloat16(w);
        *(__nv_bfloat16*)(sm + SMW_HI + c * WROW + k * 2) = hi;
        *(__nv_bfloat16*)(sm + SMW_LO + c * WROW + k * 2) =
            __float2bfloat16(w - __bfloat162float(hi));
    }

    int g = lane >> 3, lr = lane & 7;
    unsigned a_base = (unsigned)((warp_m * 16 + (g & 1) * 8 + lr) * AROW + (g >> 1) * 16);
    unsigned b_base = (unsigned)((warp_n * 16 + (g >> 1) * 8 + lr) * WROW + (g & 1) * 16);

    float creg[2] = {0.f, 0.f};
    __syncthreads();

    for (int t = 0; t < T_; t++) {
        int rp = t & 1, wp = rp ^ 1;
        const __nv_bfloat16* __restrict__ hh = g_hsp[rp][0];
        const __nv_bfloat16* __restrict__ hl = g_hsp[rp][1];

        float acc[2][4] = {};

        #define LOADA(s, kc) do {                                               \
            unsigned base_ = sb + SMA + (s) * 2 * ATILE;                        \
            _Pragma("unroll")                                                   \
            for (int p = 0; p < 8; p++) {                                       \
                int u = tid + p * 256;                                          \
                int arr = u >> 10, v = u & 1023, r = v >> 4, q = v & 15;        \
                unsigned dst = base_ + arr * ATILE + r * AROW + q * 16;         \
                const __nv_bfloat16* src = arr ? &hl[r * 1024 + (kc) * 128 + q * 8] \
                                               : &hh[r * 1024 + (kc) * 128 + q * 8]; \
                cpasync16(dst, src);                                            \
            }                                                                   \
        } while (0)

        LOADA(0, 0);
        CP_COMMIT();

        for (int ch = 0; ch < 8; ch++) {
            if (ch < 7) {
                LOADA((ch + 1) & 1, ch + 1);
                CP_COMMIT();
                CP_WAIT1();
            } else {
                CP_WAIT0();
            }
            __syncthreads();                  // staged data visible
            unsigned ab = sb + SMA + (ch & 1) * 2 * ATILE;
            #pragma unroll
            for (int ks = 0; ks < 8; ks++) {
                unsigned ahi[4], alo[4], bhi[4], blo[4];
                ldsm4(ahi, ab + a_base + ks * 32);
                ldsm4(alo, ab + ATILE + a_base + ks * 32);
                unsigned bofs = b_base + ch * 256 + ks * 32;
                ldsm4(bhi, sb + SMW_HI + bofs);
                ldsm4(blo, sb + SMW_LO + bofs);
                #pragma unroll
                for (int ni = 0; ni < 2; ni++) {
                    mma16816(acc[ni], ahi, bhi[2 * ni], bhi[2 * ni + 1]);
                    mma16816(acc[ni], alo, bhi[2 * ni], bhi[2 * ni + 1]);
                    mma16816(acc[ni], ahi, blo[2 * ni], blo[2 * ni + 1]);
                }
            }
            __syncthreads();                  // all reads done before buffer reuse
        }
        #undef LOADA

        // ---- exchange gates through SMEM ----
        #pragma unroll
        for (int ni = 0; ni < 2; ni++) {
            int c = warp_n * 16 + ni * 8 + 2 * (lane & 3);
            int b = warp_m * 16 + (lane >> 2);
            GSX(c, b)         = acc[ni][0];
            GSX(c + 1, b)     = acc[ni][1];
            GSX(c, b + 8)     = acc[ni][2];
            GSX(c + 1, b + 8) = acc[ni][3];
        }
        __syncthreads();

        // ---- pointwise gates: 512 cells, 2 per thread (stable ownership) ----
        #pragma unroll
        for (int p = 0; p < 2; p++) {
            int idx = tid + p * 256;
            int jj = idx & 7, b = idx >> 3;
            int j = j0 + jj;
            size_t xb = ((size_t)b * T_ + t) * G4 + j;
            float gi = GSX(0 * 8 + jj, b) + g_xg[xb];
            float gf = GSX(1 * 8 + jj, b) + g_xg[xb + H_];
            float gg = GSX(2 * 8 + jj, b) + g_xg[xb + 2 * H_];
            float go = GSX(3 * 8 + jj, b) + g_xg[xb + 3 * H_];
            float iv = 1.f / (1.f + __expf(-gi));
            float fv = 1.f / (1.f + __expf(-gf));
            float gv = tanhf(gg);
            float ov = 1.f / (1.f + __expf(-go));
            float cn = fv * creg[p] + iv * gv;
            creg[p] = cn;
            float hn = ov * tanhf(cn);
            int hc = b * H_ + j;
            __nv_bfloat16 hb = __float2bfloat16(hn);
            g_hsp[wp][0][hc] = hb;
            g_hsp[wp][1][hc] = __float2bfloat16(hn - __bfloat162float(hb));
            if (layer == 0)
                g_y0[((size_t)b * T_ + t) * H_ + j] = hn;
            if (t == T_ - 1) {
                g_hfin[hc] = hn;
                g_c[hc] = cn;
            }
        }

        if (t + 1 < T_)
            grid_sync((unsigned)(t + 1));
    }
}

// ---------------- write final h, c for one layer into d_out ----------------
__global__ void copy_out(float* __restrict__ out, int layer) {
    int i = blockIdx.x * blockDim.x + threadIdx.x;
    if (i < B_ * H_) {
        out[(size_t)layer * B_ * H_ + i]       = g_hfin[i];
        out[(size_t)(2 + layer) * B_ * H_ + i] = g_c[i];
    }
}

// ---------------- host ----------------
extern "C" void kernel_launch(void* const* d_in, const int* in_sizes, int n_in,
                              void* d_out, int out_size) {
    const float* x     = (const float*)d_in[0];
    const float* W_ih0 = (const float*)d_in[1];
    const float* W_hh0 = (const float*)d_in[2];
    const float* b_ih0 = (const float*)d_in[3];
    const float* b_hh0 = (const float*)d_in[4];
    const float* W_ih1 = (const float*)d_in[5];
    const float* W_hh1 = (const float*)d_in[6];
    const float* b_ih1 = (const float*)d_in[7];
    const float* b_hh1 = (const float*)d_in[8];
    float* out = (float*)d_out;

    cudaFuncSetAttribute(lstm_persist,
                         cudaFuncAttributeMaxDynamicSharedMemorySize, LP_SMEM);
    cudaFuncSetAttribute(gemm_xg_mma,
                         cudaFuncAttributeMaxDynamicSharedMemorySize, GXM_SMEM);

    // ---- layer 0 ----
    split_x<<<4096, 256>>>(x, 0, (size_t)B_ * T_ * D_);
    split_w<<<1024, 256>>>(W_ih0, (size_t)G4 * D_);
    gemm_xg_mma<<<dim3(G4 / 128, (B_ * T_) / 128), 256, GXM_SMEM>>>(D_, b_ih0, b_hh0);
    zero_state<<<256, 256>>>();
    lstm_persist<<<NBLK, NTHR, LP_SMEM>>>(W_hh0, 0);
    copy_out<<<256, 256>>>(out, 0);

    // ---- layer 1 ----
    split_x<<<4096, 256>>>(nullptr, 1, (size_t)B_ * T_ * H_);
    split_w<<<4096, 256>>>(W_ih1, (size_t)G4 * H_);
    gemm_xg_mma<<<dim3(G4 / 128, (B_ * T_) / 128), 256, GXM_SMEM>>>(H_, b_ih1, b_hh1);
    zero_state<<<256, 256>>>();
    lstm_persist<<<NBLK, NTHR, LP_SMEM>>>(W_hh1, 1);
    copy_out<<<256, 256>>>(out, 1);
}